// round 6
// baseline (speedup 1.0000x reference)
#include <cuda_runtime.h>
#include <cuda_fp16.h>
#include <cstdint>

#define TPB     512
#define TILE_M  128
#define STATE   24
#define L1D     100
#define L2D     100
#define NHEAD   27
#define ACT     6

#define NT12    13
#define NT3     4
#define KS1     2
#define KS23    7

#define S32     116    // row stride in b32 words (mod 32 = 20 -> conflict-free patterns)
#define LOW     56     // lo-plane word offset within row

// ---- smem layout (b32 word offsets) ----
#define F_BP1   0
#define F_BP2   (F_BP1 + KS1*NT12*32*4)        //  3328
#define F_BP3   (F_BP2 + KS23*NT12*32*4)       // 14976
#define F_P     (F_BP3 + KS23*NT3*32*4)        // 18560
#define F_Q     (F_P + TILE_M*S32)             // 33408
#define F_ST    (F_Q + TILE_M*S32)             // 48256  chol[128*36] + mean[128*6]
#define F_TOTAL (F_ST + TILE_M*36 + TILE_M*ACT) // 53632 b32 = 214528 B

__constant__ int c_pos[21]   = {0,6,7,12,13,14,18,19,20,21,24,25,26,27,28,30,31,32,33,34,35};
__constant__ int c_upper[15] = {1,2,3,4,5,8,9,10,11,15,16,17,22,23,29};

__device__ __forceinline__ uint32_t packh(__half a, __half b) {
    return (uint32_t)__half_as_ushort(a) | ((uint32_t)__half_as_ushort(b) << 16);
}
__device__ __forceinline__ void split2(float v0, float v1, uint32_t& hi, uint32_t& lo) {
    __half h0 = __float2half_rn(v0), h1 = __float2half_rn(v1);
    __half l0 = __float2half_rn(v0 - __half2float(h0));
    __half l1 = __float2half_rn(v1 - __half2float(h1));
    hi = packh(h0, h1); lo = packh(l0, l1);
}
// pair index -> permuted word slot: within each 8-slot block, (p&7)=q maps to 2(q&3)+(q>>2)
__device__ __forceinline__ int slotp(int p) {
    return ((p >> 3) << 3) + 2 * (p & 3) + ((p & 7) >> 2);
}

__device__ __forceinline__ void mma16(float* c, const uint32_t* a, uint32_t b0, uint32_t b1) {
    asm volatile("mma.sync.aligned.m16n8k16.row.col.f32.f16.f16.f32 "
                 "{%0,%1,%2,%3},{%4,%5,%6,%7},{%8,%9},{%0,%1,%2,%3};"
                 : "+f"(c[0]), "+f"(c[1]), "+f"(c[2]), "+f"(c[3])
                 : "r"(a[0]), "r"(a[1]), "r"(a[2]), "r"(a[3]), "r"(b0), "r"(b1));
}

extern __shared__ uint32_t smem[];

// 3-term f16 warp GEMM over permuted hi/lo planes. A loads are LDS.64.
template<int KS, int MT, int NTW>
__device__ __forceinline__ void wgemm16(const uint32_t* __restrict__ A32,
                                        const uint4* __restrict__ Bp,
                                        int NTT, int nt0, int cnt,
                                        int wrow, int g, int t, int lane,
                                        float (&c)[MT][NTW][4])
{
    #pragma unroll
    for (int mt = 0; mt < MT; mt++)
        #pragma unroll
        for (int j = 0; j < NTW; j++)
            #pragma unroll
            for (int i = 0; i < 4; i++) c[mt][j][i] = 0.0f;

    #pragma unroll 1
    for (int ks = 0; ks < KS; ks++) {
        const int sb = ks * 8 + 2 * t;      // permuted slot base -> pairs (8ks+t, 8ks+t+4)

        uint4 bfr[NTW];
        #pragma unroll
        for (int j = 0; j < NTW; j++)
            if (j < cnt) bfr[j] = Bp[(ks * NTT + nt0 + j) * 32 + lane];

        uint32_t ah[MT][4], al[MT][4];
        #pragma unroll
        for (int mt = 0; mt < MT; mt++) {
            const uint32_t* r = A32 + (wrow + 16 * mt + g) * S32 + sb;
            uint2 h0 = *reinterpret_cast<const uint2*>(r);
            uint2 h1 = *reinterpret_cast<const uint2*>(r + 8 * S32);
            uint2 l0 = *reinterpret_cast<const uint2*>(r + LOW);
            uint2 l1 = *reinterpret_cast<const uint2*>(r + LOW + 8 * S32);
            ah[mt][0] = h0.x; ah[mt][1] = h1.x; ah[mt][2] = h0.y; ah[mt][3] = h1.y;
            al[mt][0] = l0.x; al[mt][1] = l1.x; al[mt][2] = l0.y; al[mt][3] = l1.y;
        }

        #pragma unroll
        for (int term = 0; term < 3; term++)
            #pragma unroll
            for (int j = 0; j < NTW; j++) {
                if (j >= cnt) continue;
                uint32_t b0 = (term == 2) ? bfr[j].z : bfr[j].x;
                uint32_t b1 = (term == 2) ? bfr[j].w : bfr[j].y;
                #pragma unroll
                for (int mt = 0; mt < MT; mt++)
                    mma16(c[mt][j], (term == 1) ? al[mt] : ah[mt], b0, b1);
            }
    }
}

// relu + split + store into permuted planes of dst (cols < 100 only)
template<int MT, int NTW>
__device__ __forceinline__ void epi_relu16(float (&c)[MT][NTW][4], uint32_t* dst,
                                           int wrow, int nt0, int cnt, int g, int t)
{
    #pragma unroll
    for (int mt = 0; mt < MT; mt++) {
        const int row = wrow + 16 * mt + g;
        #pragma unroll
        for (int j = 0; j < NTW; j++) {
            if (j >= cnt) continue;
            const int nt = nt0 + j;
            if (nt == 12 && t >= 2) continue;
            const int sl = ((nt >> 1) << 3) + 2 * t + (nt & 1);   // slot of pair 4nt+t
            uint32_t h, l;
            split2(fmaxf(c[mt][j][0], 0.f), fmaxf(c[mt][j][1], 0.f), h, l);
            dst[row * S32 + sl] = h;  dst[row * S32 + LOW + sl] = l;
            split2(fmaxf(c[mt][j][2], 0.f), fmaxf(c[mt][j][3], 0.f), h, l);
            dst[(row + 8) * S32 + sl] = h;  dst[(row + 8) * S32 + LOW + sl] = l;
        }
    }
}

__global__ void __launch_bounds__(TPB, 1)
actor_mma(const float* __restrict__ states,
          const float* __restrict__ W1, const float* __restrict__ b1,
          const float* __restrict__ W2, const float* __restrict__ b2,
          const float* __restrict__ Wm, const float* __restrict__ bm,
          const float* __restrict__ Wc, const float* __restrict__ bc,
          float* __restrict__ out, int B)
{
    const int tid  = threadIdx.x;
    const int lane = tid & 31;
    const int wid  = tid >> 5;
    const int g    = lane >> 2;
    const int t    = lane & 3;

    // layers 1,2: M4 x N4
    const int wrow = (wid & 3) * 32;
    const int nh   = wid >> 2;
    const int nt0  = (nh == 0) ? 0 : (1 + 3 * nh);   // {0,4,7,10}
    const int ncnt = (nh == 0) ? 4 : 3;
    // head: M8 x N2
    const int wrow3 = (wid & 7) * 16;
    const int nt03  = (wid >> 3) * 2;

    uint32_t* P = smem + F_P;
    uint32_t* Q = smem + F_Q;
    float* sChol = reinterpret_cast<float*>(smem + F_ST);
    float* sMean = reinterpret_cast<float*>(smem + F_ST + TILE_M * 36);
    const uint4* Bp1 = reinterpret_cast<const uint4*>(smem + F_BP1);
    const uint4* Bp2 = reinterpret_cast<const uint4*>(smem + F_BP2);
    const uint4* Bp3 = reinterpret_cast<const uint4*>(smem + F_BP3);

    // ---- stage packed f16 hi/lo weight fragments (biases folded as K-column) ----
    for (int i = tid; i < KS1 * NT12 * 32; i += TPB) {
        int ln = i & 31, slot = i >> 5, ks = slot / NT12, nt = slot - ks * NT12;
        int n = (ln >> 2) + 8 * nt, k0 = 16 * ks + 2 * (ln & 3);
        float w[4];
        #pragma unroll
        for (int q = 0; q < 4; q++) {
            int k = k0 + (q >> 1) * 8 + (q & 1);
            w[q] = (n < L1D) ? (k < STATE ? W1[n * STATE + k] : (k == STATE ? b1[n] : 0.f)) : 0.f;
        }
        uint4 fr; uint32_t lo0, lo1;
        split2(w[0], w[1], fr.x, lo0); split2(w[2], w[3], fr.y, lo1);
        fr.z = lo0; fr.w = lo1;
        reinterpret_cast<uint4*>(smem + F_BP1)[i] = fr;
    }
    for (int i = tid; i < KS23 * NT12 * 32; i += TPB) {
        int ln = i & 31, slot = i >> 5, ks = slot / NT12, nt = slot - ks * NT12;
        int n = (ln >> 2) + 8 * nt, k0 = 16 * ks + 2 * (ln & 3);
        float w[4];
        #pragma unroll
        for (int q = 0; q < 4; q++) {
            int k = k0 + (q >> 1) * 8 + (q & 1);
            w[q] = (n < L2D) ? (k < L1D ? W2[n * L1D + k] : (k == L1D ? b2[n] : 0.f)) : 0.f;
        }
        uint4 fr; uint32_t lo0, lo1;
        split2(w[0], w[1], fr.x, lo0); split2(w[2], w[3], fr.y, lo1);
        fr.z = lo0; fr.w = lo1;
        reinterpret_cast<uint4*>(smem + F_BP2)[i] = fr;
    }
    for (int i = tid; i < KS23 * NT3 * 32; i += TPB) {
        int ln = i & 31, slot = i >> 5, ks = slot / NT3, nt = slot - ks * NT3;
        int n = (ln >> 2) + 8 * nt, k0 = 16 * ks + 2 * (ln & 3);
        float w[4];
        #pragma unroll
        for (int q = 0; q < 4; q++) {
            int k = k0 + (q >> 1) * 8 + (q & 1);
            float v = 0.f;
            if (n < ACT)        v = k < L2D ? Wm[n * L2D + k] : (k == L2D ? bm[n] : 0.f);
            else if (n < NHEAD) v = k < L2D ? Wc[(n - ACT) * L2D + k] : (k == L2D ? bc[n - ACT] : 0.f);
            w[q] = v;
        }
        uint4 fr; uint32_t lo0, lo1;
        split2(w[0], w[1], fr.x, lo0); split2(w[2], w[3], fr.y, lo1);
        fr.z = lo0; fr.w = lo1;
        reinterpret_cast<uint4*>(smem + F_BP3)[i] = fr;
    }
    // zero P and Q fully, then set persistent bias pair 50 (slot 52) in both
    for (int i = tid; i < 2 * TILE_M * S32; i += TPB) P[i] = 0u;  // P then Q contiguous
    __syncthreads();
    if (tid < TILE_M) {
        uint32_t one = packh(__float2half_rn(1.f), __ushort_as_half(0));
        P[tid * S32 + 52] = one;
        Q[tid * S32 + 52] = one;
    }
    __syncthreads();

    const int ntiles = (B + TILE_M - 1) / TILE_M;
    const int grid = gridDim.x;

    // ---- prefetch first tile's X into registers (tid<256: row=tid>>1, 3 float4) ----
    float4 px0, px1, px2;
    {
        int tile = blockIdx.x;
        if (tid < 2 * TILE_M && tile < ntiles) {
            long m = (long)tile * TILE_M + (tid >> 1); if (m >= B) m = B - 1;
            const float4* src = reinterpret_cast<const float4*>(states + m * STATE) + (tid & 1) * 3;
            px0 = src[0]; px1 = src[1]; px2 = src[2];
        }
    }

    for (int tile = blockIdx.x; tile < ntiles; tile += grid) {
        // ---- write prefetched X into P (permuted pairs 0..15) ----
        if (tid < 2 * TILE_M) {
            const int row = tid >> 1, half = tid & 1;
            uint32_t* pr = P + row * S32;
            const int pb = half * 6;                       // pair base 0 or 6
            uint32_t h, l;
            split2(px0.x, px0.y, h, l); pr[slotp(pb+0)] = h; pr[LOW + slotp(pb+0)] = l;
            split2(px0.z, px0.w, h, l); pr[slotp(pb+1)] = h; pr[LOW + slotp(pb+1)] = l;
            split2(px1.x, px1.y, h, l); pr[slotp(pb+2)] = h; pr[LOW + slotp(pb+2)] = l;
            split2(px1.z, px1.w, h, l); pr[slotp(pb+3)] = h; pr[LOW + slotp(pb+3)] = l;
            split2(px2.x, px2.y, h, l); pr[slotp(pb+4)] = h; pr[LOW + slotp(pb+4)] = l;
            split2(px2.z, px2.w, h, l); pr[slotp(pb+5)] = h; pr[LOW + slotp(pb+5)] = l;
            if (half) {
                pr[slotp(12)] = packh(__float2half_rn(1.f), __ushort_as_half(0));  // bias col 24
                pr[LOW + slotp(12)] = 0u;
                #pragma unroll
                for (int p = 13; p < 16; p++) { pr[slotp(p)] = 0u; pr[LOW + slotp(p)] = 0u; }
            }
        }
        // ---- prefetch next tile's X ----
        {
            int nxt = tile + grid;
            if (tid < 2 * TILE_M && nxt < ntiles) {
                long m = (long)nxt * TILE_M + (tid >> 1); if (m >= B) m = B - 1;
                const float4* src = reinterpret_cast<const float4*>(states + m * STATE) + (tid & 1) * 3;
                px0 = src[0]; px1 = src[1]; px2 = src[2];
            }
        }
        __syncthreads();                                   // S1: X in P ready

        // ---- layer 1: read P -> write Q ----
        {
            float c1[2][4][4];
            wgemm16<KS1, 2, 4>(P, Bp1, NT12, nt0, ncnt, wrow, g, t, lane, c1);
            epi_relu16<2, 4>(c1, Q, wrow, nt0, ncnt, g, t);
        }
        __syncthreads();                                   // S2: Q ready

        // ---- layer 2: read Q -> write P ----
        {
            float c2[2][4][4];
            wgemm16<KS23, 2, 4>(Q, Bp2, NT12, nt0, ncnt, wrow, g, t, lane, c2);
            epi_relu16<2, 4>(c2, P, wrow, nt0, ncnt, g, t);
        }
        __syncthreads();                                   // S4: P (hidden2) ready

        // ---- head: read P -> stage outputs ----
        {
            float c3[1][2][4];
            wgemm16<KS23, 1, 2>(P, Bp3, NT3, nt03, 2, wrow3, g, t, lane, c3);
            #pragma unroll
            for (int j = 0; j < 2; j++)
                #pragma unroll
                for (int i = 0; i < 4; i++) {
                    int row = wrow3 + g + ((i >= 2) ? 8 : 0);
                    int col = 8 * (nt03 + j) + 2 * t + (i & 1);
                    float v = c3[0][j][i];
                    if (col < ACT) {
                        sMean[row * ACT + col] = tanhf(v);
                    } else if (col < NHEAD) {
                        float sp = fmaxf(v, 0.f) + log1pf(expf(-fabsf(v)));
                        sChol[row * 36 + c_pos[col - ACT]] = sp;
                    }
                }
            if (tid < TILE_M) {
                #pragma unroll
                for (int j = 0; j < 15; j++) sChol[tid * 36 + c_upper[j]] = 0.0f;
            }
        }
        __syncthreads();                                   // S5: staged

        // ---- coalesced writeback (no trailing barrier; S1 next iter guards) ----
        if ((tile + 1) * TILE_M <= B) {
            float4* pm = reinterpret_cast<float4*>(out + (size_t)tile * (TILE_M * ACT));
            const float4* sm4 = reinterpret_cast<const float4*>(sMean);
            for (int i = tid; i < TILE_M * ACT / 4; i += TPB) pm[i] = sm4[i];
            float4* pc = reinterpret_cast<float4*>(out + (size_t)B * ACT + (size_t)tile * (TILE_M * 36));
            const float4* sc4 = reinterpret_cast<const float4*>(sChol);
            for (int i = tid; i < TILE_M * 36 / 4; i += TPB) pc[i] = sc4[i];
        } else {
            int nrow = B - tile * TILE_M;
            for (int i = tid; i < nrow * ACT; i += TPB)
                out[(size_t)tile * (TILE_M * ACT) + i] = sMean[i];
            for (int i = tid; i < nrow * 36; i += TPB)
                out[(size_t)B * ACT + (size_t)tile * (TILE_M * 36) + i] = sChol[i];
        }
        __syncthreads();                                   // S6: stage free before next head epi
    }
}

extern "C" void kernel_launch(void* const* d_in, const int* in_sizes, int n_in,
                              void* d_out, int out_size)
{
    const float* states = (const float*)d_in[0];
    const float* W1 = (const float*)d_in[1];
    const float* b1 = (const float*)d_in[2];
    const float* W2 = (const float*)d_in[3];
    const float* b2 = (const float*)d_in[4];
    const float* Wm = (const float*)d_in[5];
    const float* bm = (const float*)d_in[6];
    const float* Wc = (const float*)d_in[7];
    const float* bc = (const float*)d_in[8];
    float* out = (float*)d_out;

    const int B = in_sizes[0] / STATE;
    const int ntiles = (B + TILE_M - 1) / TILE_M;
    const size_t smem_bytes = (size_t)F_TOTAL * 4;   // ~214.5 KB

    cudaFuncSetAttribute(actor_mma,
                         cudaFuncAttributeMaxDynamicSharedMemorySize,
                         (int)smem_bytes);

    int grid = ntiles < 152 ? ntiles : 152;          // GB300: 152 SMs
    actor_mma<<<grid, TPB, smem_bytes>>>(states, W1, b1, W2, b2,
                                         Wm, bm, Wc, bc, out, B);
}

// round 7
// speedup vs baseline: 1.2743x; 1.2743x over previous
#include <cuda_runtime.h>
#include <cuda_fp16.h>
#include <cstdint>

#define TPB     256
#define TILE_M  64
#define STATE   24
#define L1D     100
#define L2D     100
#define NHEAD   27
#define ACT     6

#define NT12    13
#define NT3     4
#define KS1     2
#define KS23    7

#define S1_32   36
#define LO1     16
#define S2_32   116
#define LO2     56

// ---- smem layout (b32 word offsets) ----
#define F_BP1   0
#define F_BP2   (F_BP1 + KS1*NT12*32*4)         //  3328
#define F_BP3   (F_BP2 + KS23*NT12*32*4)        // 14976
#define F_AS1   (F_BP3 + KS23*NT3*32*4)         // 18560  (overlaid: chol f32 64*36)
#define F_AS2   (F_AS1 + TILE_M*S1_32)          // 20864
#define F_MEAN  (F_AS2 + TILE_M*S2_32)          // 28288
#define F_TOTAL (F_MEAN + TILE_M*ACT)           // 28672 words = 114688 B

__constant__ int c_pos[21]   = {0,6,7,12,13,14,18,19,20,21,24,25,26,27,28,30,31,32,33,34,35};
__constant__ int c_upper[15] = {1,2,3,4,5,8,9,10,11,15,16,17,22,23,29};

__device__ __forceinline__ uint32_t packh(__half a, __half b) {
    return (uint32_t)__half_as_ushort(a) | ((uint32_t)__half_as_ushort(b) << 16);
}
__device__ __forceinline__ void split2(float v0, float v1, uint32_t& hi, uint32_t& lo) {
    __half h0 = __float2half_rn(v0), h1 = __float2half_rn(v1);
    __half l0 = __float2half_rn(v0 - __half2float(h0));
    __half l1 = __float2half_rn(v1 - __half2float(h1));
    hi = packh(h0, h1); lo = packh(l0, l1);
}

__device__ __forceinline__ void mma16(float* c, const uint32_t* a, uint32_t b0, uint32_t b1) {
    asm volatile("mma.sync.aligned.m16n8k16.row.col.f32.f16.f16.f32 "
                 "{%0,%1,%2,%3},{%4,%5,%6,%7},{%8,%9},{%0,%1,%2,%3};"
                 : "+f"(c[0]), "+f"(c[1]), "+f"(c[2]), "+f"(c[3])
                 : "r"(a[0]), "r"(a[1]), "r"(a[2]), "r"(a[3]), "r"(b0), "r"(b1));
}

extern __shared__ uint32_t smem[];

// 3-term f16 warp GEMM (R5-proven structure: LDS.32 A loads, term-major issue)
template<int KS, int MT, int NTW>
__device__ __forceinline__ void wgemm16(const uint32_t* __restrict__ A32, int S32, int LO,
                                        const uint4* __restrict__ Bp,
                                        int NTT, int nt0, int cnt,
                                        int wrow, int g, int t, int lane,
                                        float (&c)[MT][NTW][4])
{
    #pragma unroll
    for (int mt = 0; mt < MT; mt++)
        #pragma unroll
        for (int j = 0; j < NTW; j++)
            #pragma unroll
            for (int i = 0; i < 4; i++) c[mt][j][i] = 0.0f;

    #pragma unroll 1
    for (int ks = 0; ks < KS; ks++) {
        const int kb = ks * 8 + t;

        uint4 bfr[NTW];
        #pragma unroll
        for (int j = 0; j < NTW; j++)
            if (j < cnt) bfr[j] = Bp[(ks * NTT + nt0 + j) * 32 + lane];

        uint32_t ah[MT][4], al[MT][4];
        #pragma unroll
        for (int mt = 0; mt < MT; mt++) {
            const uint32_t* r0 = A32 + (wrow + 16 * mt + g) * S32;
            const uint32_t* r1 = r0 + 8 * S32;
            ah[mt][0] = r0[kb];          ah[mt][1] = r1[kb];
            ah[mt][2] = r0[kb + 4];      ah[mt][3] = r1[kb + 4];
            al[mt][0] = r0[kb + LO];     al[mt][1] = r1[kb + LO];
            al[mt][2] = r0[kb + LO + 4]; al[mt][3] = r1[kb + LO + 4];
        }

        #pragma unroll
        for (int term = 0; term < 3; term++)
            #pragma unroll
            for (int j = 0; j < NTW; j++) {
                if (j >= cnt) continue;
                uint32_t b0 = (term == 2) ? bfr[j].z : bfr[j].x;
                uint32_t b1 = (term == 2) ? bfr[j].w : bfr[j].y;
                #pragma unroll
                for (int mt = 0; mt < MT; mt++)
                    mma16(c[mt][j], (term == 1) ? al[mt] : ah[mt], b0, b1);
            }
    }
}

template<int MT, int NTW>
__device__ __forceinline__ void epi_relu16(float (&c)[MT][NTW][4], uint32_t* A2,
                                           int wrow, int nt0, int cnt, int g, int t)
{
    #pragma unroll
    for (int mt = 0; mt < MT; mt++) {
        const int row = wrow + 16 * mt + g;
        #pragma unroll
        for (int j = 0; j < NTW; j++) {
            if (j >= cnt) continue;
            const int nt = nt0 + j;
            if (nt == 12 && t >= 2) continue;      // cols >= 100
            const int pi = 4 * nt + t;
            uint32_t h, l;
            split2(fmaxf(c[mt][j][0], 0.f), fmaxf(c[mt][j][1], 0.f), h, l);
            A2[row * S2_32 + pi] = h;  A2[row * S2_32 + LO2 + pi] = l;
            split2(fmaxf(c[mt][j][2], 0.f), fmaxf(c[mt][j][3], 0.f), h, l);
            A2[(row + 8) * S2_32 + pi] = h;  A2[(row + 8) * S2_32 + LO2 + pi] = l;
        }
    }
}

__global__ void __launch_bounds__(TPB, 2)
actor_mma(const float* __restrict__ states,
          const float* __restrict__ W1, const float* __restrict__ b1,
          const float* __restrict__ W2, const float* __restrict__ b2,
          const float* __restrict__ Wm, const float* __restrict__ bm,
          const float* __restrict__ Wc, const float* __restrict__ bc,
          float* __restrict__ out, int B)
{
    const int tid  = threadIdx.x;
    const int lane = tid & 31;
    const int wid  = tid >> 5;
    const int g    = lane >> 2;
    const int t    = lane & 3;

    // layers 1,2 (M=64): M2 x N4 -> warp: 32 rows, nt group
    const int wrow = (wid & 1) * 32;
    const int nh   = wid >> 1;
    const int nt0  = (nh == 0) ? 0 : (1 + 3 * nh);   // {0,4,7,10}
    const int ncnt = (nh == 0) ? 4 : 3;
    // head (M=64, N=32): M4 x N2
    const int wrow3 = (wid & 3) * 16;
    const int nt03  = (wid >> 2) * 2;

    uint32_t* As1 = smem + F_AS1;
    uint32_t* As2 = smem + F_AS2;
    float* sMean  = reinterpret_cast<float*>(smem + F_MEAN);
    float* sChol  = reinterpret_cast<float*>(smem + F_AS1);   // overlay (64*36 words)
    const uint4* Bp1 = reinterpret_cast<const uint4*>(smem + F_BP1);
    const uint4* Bp2 = reinterpret_cast<const uint4*>(smem + F_BP2);
    const uint4* Bp3 = reinterpret_cast<const uint4*>(smem + F_BP3);

    // ---- stage packed f16 hi/lo weight fragments (biases folded as K-column) ----
    for (int i = tid; i < KS1 * NT12 * 32; i += TPB) {
        int ln = i & 31, slot = i >> 5, ks = slot / NT12, nt = slot - ks * NT12;
        int n = (ln >> 2) + 8 * nt, k0 = 16 * ks + 2 * (ln & 3);
        float w[4];
        #pragma unroll
        for (int q = 0; q < 4; q++) {
            int k = k0 + (q >> 1) * 8 + (q & 1);
            w[q] = (n < L1D) ? (k < STATE ? W1[n * STATE + k] : (k == STATE ? b1[n] : 0.f)) : 0.f;
        }
        uint4 fr; uint32_t lo0, lo1;
        split2(w[0], w[1], fr.x, lo0); split2(w[2], w[3], fr.y, lo1);
        fr.z = lo0; fr.w = lo1;
        reinterpret_cast<uint4*>(smem + F_BP1)[i] = fr;
    }
    for (int i = tid; i < KS23 * NT12 * 32; i += TPB) {
        int ln = i & 31, slot = i >> 5, ks = slot / NT12, nt = slot - ks * NT12;
        int n = (ln >> 2) + 8 * nt, k0 = 16 * ks + 2 * (ln & 3);
        float w[4];
        #pragma unroll
        for (int q = 0; q < 4; q++) {
            int k = k0 + (q >> 1) * 8 + (q & 1);
            w[q] = (n < L2D) ? (k < L1D ? W2[n * L1D + k] : (k == L1D ? b2[n] : 0.f)) : 0.f;
        }
        uint4 fr; uint32_t lo0, lo1;
        split2(w[0], w[1], fr.x, lo0); split2(w[2], w[3], fr.y, lo1);
        fr.z = lo0; fr.w = lo1;
        reinterpret_cast<uint4*>(smem + F_BP2)[i] = fr;
    }
    for (int i = tid; i < KS23 * NT3 * 32; i += TPB) {
        int ln = i & 31, slot = i >> 5, ks = slot / NT3, nt = slot - ks * NT3;
        int n = (ln >> 2) + 8 * nt, k0 = 16 * ks + 2 * (ln & 3);
        float w[4];
        #pragma unroll
        for (int q = 0; q < 4; q++) {
            int k = k0 + (q >> 1) * 8 + (q & 1);
            float v = 0.f;
            if (n < ACT)        v = k < L2D ? Wm[n * L2D + k] : (k == L2D ? bm[n] : 0.f);
            else if (n < NHEAD) v = k < L2D ? Wc[(n - ACT) * L2D + k] : (k == L2D ? bc[n - ACT] : 0.f);
            w[q] = v;
        }
        uint4 fr; uint32_t lo0, lo1;
        split2(w[0], w[1], fr.x, lo0); split2(w[2], w[3], fr.y, lo1);
        fr.z = lo0; fr.w = lo1;
        reinterpret_cast<uint4*>(smem + F_BP3)[i] = fr;
    }
    // zero As2 then set persistent bias pair 50 (col 100); pads 51..55 stay 0
    for (int i = tid; i < TILE_M * S2_32; i += TPB) As2[i] = 0u;
    __syncthreads();
    if (tid < TILE_M)
        As2[tid * S2_32 + 50] = packh(__float2half_rn(1.f), __ushort_as_half(0));
    __syncthreads();

    const int ntiles = (B + TILE_M - 1) / TILE_M;

    for (int tile = blockIdx.x; tile < ntiles; tile += gridDim.x) {
        // ---- load X rows -> As1 hi/lo planes (2 threads per row) ----
        if (tid < 2 * TILE_M) {
            const int row = tid >> 1, half = tid & 1;
            long m = (long)tile * TILE_M + row; if (m >= B) m = B - 1;
            const float4* src = reinterpret_cast<const float4*>(states + m * STATE) + half * 3;
            uint32_t* rh = As1 + row * S1_32 + half * 6;
            float4 v0 = src[0], v1 = src[1], v2 = src[2];
            uint32_t h, l;
            split2(v0.x, v0.y, h, l); rh[0] = h; rh[LO1 + 0] = l;
            split2(v0.z, v0.w, h, l); rh[1] = h; rh[LO1 + 1] = l;
            split2(v1.x, v1.y, h, l); rh[2] = h; rh[LO1 + 2] = l;
            split2(v1.z, v1.w, h, l); rh[3] = h; rh[LO1 + 3] = l;
            split2(v2.x, v2.y, h, l); rh[4] = h; rh[LO1 + 4] = l;
            split2(v2.z, v2.w, h, l); rh[5] = h; rh[LO1 + 5] = l;
            if (half) {
                uint32_t* rr = As1 + row * S1_32;
                rr[12] = packh(__float2half_rn(1.f), __ushort_as_half(0));  // bias col 24
                rr[LO1 + 12] = 0u;
                #pragma unroll
                for (int p = 13; p < 16; p++) { rr[p] = 0u; rr[LO1 + p] = 0u; }
            }
        }
        __syncthreads();                                   // S1

        // ---- layer 1: As1 -> As2 ----
        {
            float c1[2][4][4];
            wgemm16<KS1, 2, 4>(As1, S1_32, LO1, Bp1, NT12, nt0, ncnt, wrow, g, t, lane, c1);
            epi_relu16<2, 4>(c1, As2, wrow, nt0, ncnt, g, t);
        }
        __syncthreads();                                   // S2

        // ---- layer 2: As2 -> As2 ----
        {
            float c2[2][4][4];
            wgemm16<KS23, 2, 4>(As2, S2_32, LO2, Bp2, NT12, nt0, ncnt, wrow, g, t, lane, c2);
            __syncthreads();                               // S3: reads done
            epi_relu16<2, 4>(c2, As2, wrow, nt0, ncnt, g, t);
        }
        __syncthreads();                                   // S4

        // ---- head gemm + activation scatter ----
        {
            float c3[1][2][4];
            wgemm16<KS23, 1, 2>(As2, S2_32, LO2, Bp3, NT3, nt03, 2, wrow3, g, t, lane, c3);
            #pragma unroll
            for (int j = 0; j < 2; j++)
                #pragma unroll
                for (int i = 0; i < 4; i++) {
                    int row = wrow3 + g + ((i >= 2) ? 8 : 0);
                    int col = 8 * (nt03 + j) + 2 * t + (i & 1);
                    float v = c3[0][j][i];
                    if (col < ACT) {
                        sMean[row * ACT + col] = tanhf(v);
                    } else if (col < NHEAD) {
                        float sp = fmaxf(v, 0.f) + log1pf(expf(-fabsf(v)));
                        sChol[row * 36 + c_pos[col - ACT]] = sp;
                    }
                }
            if (tid < TILE_M) {
                #pragma unroll
                for (int j = 0; j < 15; j++) sChol[tid * 36 + c_upper[j]] = 0.0f;
            }
        }
        __syncthreads();                                   // S5

        // ---- coalesced writeback ----
        if ((tile + 1) * TILE_M <= B) {
            float4* pm = reinterpret_cast<float4*>(out + (size_t)tile * (TILE_M * ACT));
            const float4* sm4 = reinterpret_cast<const float4*>(sMean);
            for (int i = tid; i < TILE_M * ACT / 4; i += TPB) pm[i] = sm4[i];
            float4* pc = reinterpret_cast<float4*>(out + (size_t)B * ACT + (size_t)tile * (TILE_M * 36));
            const float4* sc4 = reinterpret_cast<const float4*>(sChol);
            for (int i = tid; i < TILE_M * 36 / 4; i += TPB) pc[i] = sc4[i];
        } else {
            int nrow = B - tile * TILE_M;
            for (int i = tid; i < nrow * ACT; i += TPB)
                out[(size_t)tile * (TILE_M * ACT) + i] = sMean[i];
            for (int i = tid; i < nrow * 36; i += TPB)
                out[(size_t)B * ACT + (size_t)tile * (TILE_M * 36) + i] = sChol[i];
        }
        __syncthreads();                                   // S6 (As1 overlay reuse)
    }
}

extern "C" void kernel_launch(void* const* d_in, const int* in_sizes, int n_in,
                              void* d_out, int out_size)
{
    const float* states = (const float*)d_in[0];
    const float* W1 = (const float*)d_in[1];
    const float* b1 = (const float*)d_in[2];
    const float* W2 = (const float*)d_in[3];
    const float* b2 = (const float*)d_in[4];
    const float* Wm = (const float*)d_in[5];
    const float* bm = (const float*)d_in[6];
    const float* Wc = (const float*)d_in[7];
    const float* bc = (const float*)d_in[8];
    float* out = (float*)d_out;

    const int B = in_sizes[0] / STATE;
    const int ntiles = (B + TILE_M - 1) / TILE_M;
    const size_t smem_bytes = (size_t)F_TOTAL * 4;   // 114688 B = 112 KB

    cudaFuncSetAttribute(actor_mma,
                         cudaFuncAttributeMaxDynamicSharedMemorySize,
                         (int)smem_bytes);

    int grid = ntiles < 304 ? ntiles : 304;          // 2 CTAs x 152 SMs
    actor_mma<<<grid, TPB, smem_bytes>>>(states, W1, b1, W2, b2,
                                         Wm, bm, Wc, bc, out, B);
}